// round 1
// baseline (speedup 1.0000x reference)
#include <cuda_runtime.h>

#define MAXN 100000
#define MAXE 1600000
#define NF 6
#define H1 64
#define D 32

// ---------------- scratch (static device globals; no allocation) -------------
__device__ float g_g1[MAXN * D];      // conv1 source-scaled features
__device__ float g_g2[MAXN * D];      // conv2 source-scaled features
__device__ int   g_cnt[MAXN];         // in-degree histogram (without self loop)
__device__ int   g_rowptr[MAXN + 1];  // CSC row pointers (by dst)
__device__ int   g_cur[MAXN];         // fill cursors
__device__ float g_dinv[MAXN];        // rsqrt(indeg + 1)
__device__ int   g_csc[MAXE];         // source ids grouped by dst
__device__ int   g_part[128];         // scan partials
__device__ int   g_is64;              // edge_index dtype flag

// ---------------- edge dtype detection --------------------------------------
// int64 values < 2^31 => every odd int32 word is 0. For int32 data, odd words
// are random node ids in [0,100000): P(all 2048 zero) ~ 0.
__global__ void k_detect(const int* __restrict__ e) {
    __shared__ int s;
    if (threadIdx.x == 0) s = 0;
    __syncthreads();
    int v = 0;
    for (int i = threadIdx.x; i < 2048; i += blockDim.x) v |= e[2 * i + 1];
    atomicOr(&s, v);
    __syncthreads();
    if (threadIdx.x == 0) g_is64 = (s == 0) ? 1 : 0;
}

__device__ __forceinline__ int load_dst(const void* e, int i, int E) {
    if (g_is64) return (int)((const long long*)e)[(long long)E + i];
    return ((const int*)e)[E + i];
}
__device__ __forceinline__ int load_src(const void* e, int i, int E) {
    if (g_is64) return (int)((const long long*)e)[i];
    return ((const int*)e)[i];
}

// ---------------- CSC build --------------------------------------------------
__global__ void k_zero(int n) {
    int i = blockIdx.x * blockDim.x + threadIdx.x;
    if (i < n) g_cnt[i] = 0;
}

__global__ void k_hist(const void* __restrict__ e, int E) {
    int i = blockIdx.x * blockDim.x + threadIdx.x;
    if (i >= E) return;
    atomicAdd(&g_cnt[load_dst(e, i, E)], 1);
}

__global__ void k_scanA(int n) {  // 1024 threads per block, chunk of 1024
    __shared__ int sh[1024];
    int i = blockIdx.x * 1024 + threadIdx.x;
    int v = (i < n) ? g_cnt[i] : 0;
    sh[threadIdx.x] = v;
    __syncthreads();
    for (int off = 1; off < 1024; off <<= 1) {
        int t = (threadIdx.x >= off) ? sh[threadIdx.x - off] : 0;
        __syncthreads();
        sh[threadIdx.x] += t;
        __syncthreads();
    }
    if (i < n) g_rowptr[i] = sh[threadIdx.x] - v;  // exclusive
    if (threadIdx.x == 1023) g_part[blockIdx.x] = sh[1023];
}

__global__ void k_scanB(int nblk) {  // single block of 128, nblk <= 128
    __shared__ int sh[128];
    int t = threadIdx.x;
    int v = (t < nblk) ? g_part[t] : 0;
    sh[t] = v;
    __syncthreads();
    for (int off = 1; off < 128; off <<= 1) {
        int u = (t >= off) ? sh[t - off] : 0;
        __syncthreads();
        sh[t] += u;
        __syncthreads();
    }
    if (t < nblk) g_part[t] = sh[t] - v;  // exclusive
}

__global__ void k_scanC(int n, int E) {
    int i = blockIdx.x * blockDim.x + threadIdx.x;
    if (i == 0) g_rowptr[n] = E;
    if (i >= n) return;
    int r = g_rowptr[i] + g_part[i >> 10];
    g_rowptr[i] = r;
    g_cur[i] = r;
    g_dinv[i] = rsqrtf((float)(g_cnt[i] + 1));
}

__global__ void k_fill(const void* __restrict__ e, int E) {
    int i = blockIdx.x * blockDim.x + threadIdx.x;
    if (i >= E) return;
    int s = load_src(e, i, E);
    int d = load_dst(e, i, E);
    int pos = atomicAdd(&g_cur[d], 1);
    g_csc[pos] = s;
}

// ---------------- fused embed MLP + conv1 linear -----------------------------
// warp per node, lane = output channel. g1 = ((MLP(x)) @ Wg1) * dinv
__global__ void __launch_bounds__(256) k_embed(
    const float* __restrict__ x,
    const float* __restrict__ We1, const float* __restrict__ be1,
    const float* __restrict__ We2, const float* __restrict__ be2,
    const float* __restrict__ Wg1, int n)
{
    __shared__ float sWe1[NF * H1], sbe1[H1], sWe2[H1 * D], sbe2[D], sWg1[D * D];
    for (int i = threadIdx.x; i < NF * H1; i += 256) sWe1[i] = We1[i];
    for (int i = threadIdx.x; i < H1;      i += 256) sbe1[i] = be1[i];
    for (int i = threadIdx.x; i < H1 * D;  i += 256) sWe2[i] = We2[i];
    for (int i = threadIdx.x; i < D;       i += 256) sbe2[i] = be2[i];
    for (int i = threadIdx.x; i < D * D;   i += 256) sWg1[i] = Wg1[i];
    __syncthreads();

    int warp = (blockIdx.x * 256 + threadIdx.x) >> 5;
    int lane = threadIdx.x & 31;
    if (warp >= n) return;

    float xv = (lane < NF) ? x[warp * NF + lane] : 0.f;
    float a = sbe1[lane], b = sbe1[lane + 32];
#pragma unroll
    for (int k = 0; k < NF; k++) {
        float xk = __shfl_sync(0xffffffffu, xv, k);
        a = fmaf(xk, sWe1[k * H1 + lane], a);
        b = fmaf(xk, sWe1[k * H1 + lane + 32], b);
    }
    a = tanhf(a);
    b = tanhf(b);

    float acc = sbe2[lane];
#pragma unroll
    for (int j = 0; j < 32; j++) {
        float ha = __shfl_sync(0xffffffffu, a, j);
        float hb = __shfl_sync(0xffffffffu, b, j);
        acc = fmaf(ha, sWe2[j * D + lane], acc);
        acc = fmaf(hb, sWe2[(j + 32) * D + lane], acc);
    }
    float h = tanhf(acc);

    float hw = 0.f;
#pragma unroll
    for (int k = 0; k < 32; k++)
        hw = fmaf(__shfl_sync(0xffffffffu, h, k), sWg1[k * D + lane], hw);

    g_g1[warp * D + lane] = hw * g_dinv[warp];
}

// ---------------- gather conv1 + relu + conv2 linear -------------------------
__global__ void __launch_bounds__(256) k_gather1(
    const float* __restrict__ Wg2, const float* __restrict__ bg1, int n)
{
    __shared__ float sW[D * D], sb[D];
    for (int i = threadIdx.x; i < D * D; i += 256) sW[i] = Wg2[i];
    for (int i = threadIdx.x; i < D;     i += 256) sb[i] = bg1[i];
    __syncthreads();

    int warp = (blockIdx.x * 256 + threadIdx.x) >> 5;
    int lane = threadIdx.x & 31;
    if (warp >= n) return;

    int beg = g_rowptr[warp], end = g_rowptr[warp + 1];
    float acc = g_g1[warp * D + lane];  // self loop (already source-scaled)
    for (int e = beg; e < end; e++) {
        int s = g_csc[e];
        acc += g_g1[s * D + lane];
    }
    float di = g_dinv[warp];
    float h = fmaxf(fmaf(acc, di, sb[lane]), 0.f);

    float hw = 0.f;
#pragma unroll
    for (int k = 0; k < 32; k++)
        hw = fmaf(__shfl_sync(0xffffffffu, h, k), sW[k * D + lane], hw);

    g_g2[warp * D + lane] = hw * di;
}

// ---------------- gather conv2 + relu + output MLP ---------------------------
__global__ void __launch_bounds__(256) k_post(
    const float* __restrict__ bg2,
    const float* __restrict__ Wp1, const float* __restrict__ bp1,
    const float* __restrict__ Wp2, const float* __restrict__ bp2,
    float* __restrict__ out, int n)
{
    __shared__ float sW[D * D], sbg[D], sb1[D], sW2[D];
    __shared__ float sb2;
    for (int i = threadIdx.x; i < D * D; i += 256) sW[i] = Wp1[i];
    for (int i = threadIdx.x; i < D;     i += 256) { sbg[i] = bg2[i]; sb1[i] = bp1[i]; sW2[i] = Wp2[i]; }
    if (threadIdx.x == 0) sb2 = bp2[0];
    __syncthreads();

    int warp = (blockIdx.x * 256 + threadIdx.x) >> 5;
    int lane = threadIdx.x & 31;
    if (warp >= n) return;

    int beg = g_rowptr[warp], end = g_rowptr[warp + 1];
    float acc = g_g2[warp * D + lane];
    for (int e = beg; e < end; e++) {
        int s = g_csc[e];
        acc += g_g2[s * D + lane];
    }
    float di = g_dinv[warp];
    float h = fmaxf(fmaf(acc, di, sbg[lane]), 0.f);

    float t = sb1[lane];
#pragma unroll
    for (int k = 0; k < 32; k++)
        t = fmaf(__shfl_sync(0xffffffffu, h, k), sW[k * D + lane], t);

    float u = tanhf(t) * sW2[lane];
#pragma unroll
    for (int off = 16; off; off >>= 1)
        u += __shfl_xor_sync(0xffffffffu, u, off);

    if (lane == 0) out[warp] = tanhf(u + sb2);
}

// ---------------- launch ------------------------------------------------------
extern "C" void kernel_launch(void* const* d_in, const int* in_sizes, int n_in,
                              void* d_out, int out_size)
{
    const float* x   = (const float*)d_in[0];
    const void*  ei  = d_in[1];
    const float* We1 = (const float*)d_in[2];
    const float* be1 = (const float*)d_in[3];
    const float* We2 = (const float*)d_in[4];
    const float* be2 = (const float*)d_in[5];
    const float* Wg1 = (const float*)d_in[6];
    const float* bg1 = (const float*)d_in[7];
    const float* Wg2 = (const float*)d_in[8];
    const float* bg2 = (const float*)d_in[9];
    const float* Wp1 = (const float*)d_in[10];
    const float* bp1 = (const float*)d_in[11];
    const float* Wp2 = (const float*)d_in[12];
    const float* bp2 = (const float*)d_in[13];

    int N = in_sizes[0] / NF;
    int E = in_sizes[1] / 2;
    if (N > MAXN) N = MAXN;
    if (E > MAXE) E = MAXE;

    k_detect<<<1, 256>>>((const int*)ei);
    k_zero<<<(N + 255) / 256, 256>>>(N);
    k_hist<<<(E + 255) / 256, 256>>>(ei, E);
    int nblk = (N + 1023) / 1024;
    k_scanA<<<nblk, 1024>>>(N);
    k_scanB<<<1, 128>>>(nblk);
    k_scanC<<<(N + 255) / 256, 256>>>(N, E);
    k_fill<<<(E + 255) / 256, 256>>>(ei, E);

    int nodeBlocks = (N * 32 + 255) / 256;
    k_embed<<<nodeBlocks, 256>>>(x, We1, be1, We2, be2, Wg1, N);
    k_gather1<<<nodeBlocks, 256>>>(Wg2, bg1, N);
    k_post<<<nodeBlocks, 256>>>(bg2, Wp1, bp1, Wp2, bp2, (float*)d_out, N);
}

// round 2
// speedup vs baseline: 1.0091x; 1.0091x over previous
#include <cuda_runtime.h>
#include <cuda_fp16.h>

#define MAXN 100000
#define MAXE 1600000
#define NF 6
#define H1 64
#define D 32

// ---------------- scratch (static device globals; no allocation) -------------
__device__ __half g_g1h[MAXN * D];    // conv1 source-scaled features (fp16)
__device__ __half g_g2h[MAXN * D];    // conv2 source-scaled features (fp16)
__device__ int    g_cnt[MAXN];        // in-degree histogram (without self loop)
__device__ int    g_rowptr[MAXN + 1]; // CSC row pointers (by dst)
__device__ int    g_cur[MAXN];        // fill cursors
__device__ float  g_dinv[MAXN];       // rsqrt(indeg + 1)
__device__ int    g_csc[MAXE];        // source ids grouped by dst
__device__ int    g_part[128];        // scan partials
__device__ int    g_is64;             // edge_index dtype flag

// ---------------- init: dtype detect (block 0) + zero counters ---------------
__global__ void k_init(const int* __restrict__ e, int n) {
    int i = blockIdx.x * blockDim.x + threadIdx.x;
    if (i < n) g_cnt[i] = 0;
    if (blockIdx.x == 0) {
        __shared__ int s;
        if (threadIdx.x == 0) s = 0;
        __syncthreads();
        int v = 0;
        for (int j = threadIdx.x; j < 2048; j += blockDim.x) v |= e[2 * j + 1];
        atomicOr(&s, v);
        __syncthreads();
        if (threadIdx.x == 0) g_is64 = (s == 0) ? 1 : 0;
    }
}

__device__ __forceinline__ int load_dst(const void* e, int i, int E) {
    if (g_is64) return ((const int*)e)[2 * (E + i)];
    return ((const int*)e)[E + i];
}
__device__ __forceinline__ int load_src(const void* e, int i, int E) {
    if (g_is64) return ((const int*)e)[2 * i];
    return ((const int*)e)[i];
}

// ---------------- CSC build --------------------------------------------------
__global__ void k_hist(const void* __restrict__ e, int E) {
    int i = blockIdx.x * blockDim.x + threadIdx.x;
    if (i >= E) return;
    atomicAdd(&g_cnt[load_dst(e, i, E)], 1);
}

__global__ void __launch_bounds__(1024) k_scanA(int n) {
    __shared__ int wsum[32];
    int i = blockIdx.x * 1024 + threadIdx.x;
    int lane = threadIdx.x & 31, wid = threadIdx.x >> 5;
    int v = (i < n) ? g_cnt[i] : 0;
    int s = v;
#pragma unroll
    for (int off = 1; off < 32; off <<= 1) {
        int t = __shfl_up_sync(0xffffffffu, s, off);
        if (lane >= off) s += t;
    }
    if (lane == 31) wsum[wid] = s;
    __syncthreads();
    if (wid == 0) {
        int w = wsum[lane];
        int ws = w;
#pragma unroll
        for (int off = 1; off < 32; off <<= 1) {
            int t = __shfl_up_sync(0xffffffffu, ws, off);
            if (lane >= off) ws += t;
        }
        wsum[lane] = ws - w;  // exclusive warp offsets
    }
    __syncthreads();
    int incl = s + wsum[wid];
    if (i < n) g_rowptr[i] = incl - v;  // exclusive within block
    if (threadIdx.x == 1023) g_part[blockIdx.x] = incl;
}

__global__ void k_scanB(int nblk) {  // single block of 128, nblk <= 128
    __shared__ int sh[128];
    int t = threadIdx.x;
    int v = (t < nblk) ? g_part[t] : 0;
    sh[t] = v;
    __syncthreads();
    for (int off = 1; off < 128; off <<= 1) {
        int u = (t >= off) ? sh[t - off] : 0;
        __syncthreads();
        sh[t] += u;
        __syncthreads();
    }
    if (t < nblk) g_part[t] = sh[t] - v;  // exclusive
}

__global__ void k_scanC(int n, int E) {
    int i = blockIdx.x * blockDim.x + threadIdx.x;
    if (i == 0) g_rowptr[n] = E;
    if (i >= n) return;
    int r = g_rowptr[i] + g_part[i >> 10];
    g_rowptr[i] = r;
    g_cur[i] = r;
    g_dinv[i] = rsqrtf((float)(g_cnt[i] + 1));
}

// ---------------- fused: CSC fill (blocks [0,fillBlocks)) + embed MLP --------
// fill and embed are independent (both depend on scanC) -> overlap on-chip.
__global__ void __launch_bounds__(256) k_fill_embed(
    const void* __restrict__ e, int E, int fillBlocks,
    const float* __restrict__ x,
    const float* __restrict__ We1, const float* __restrict__ be1,
    const float* __restrict__ We2, const float* __restrict__ be2,
    const float* __restrict__ Wg1, int n)
{
    if ((int)blockIdx.x < fillBlocks) {
        int i = blockIdx.x * 256 + threadIdx.x;
        if (i >= E) return;
        int s = load_src(e, i, E);
        int d = load_dst(e, i, E);
        int pos = atomicAdd(&g_cur[d], 1);
        g_csc[pos] = s;
        return;
    }

    __shared__ float sWe1[NF * H1], sbe1[H1], sWe2[H1 * D], sbe2[D], sWg1[D * D];
    for (int i = threadIdx.x; i < NF * H1; i += 256) sWe1[i] = We1[i];
    for (int i = threadIdx.x; i < H1;      i += 256) sbe1[i] = be1[i];
    for (int i = threadIdx.x; i < H1 * D;  i += 256) sWe2[i] = We2[i];
    for (int i = threadIdx.x; i < D;       i += 256) sbe2[i] = be2[i];
    for (int i = threadIdx.x; i < D * D;   i += 256) sWg1[i] = Wg1[i];
    __syncthreads();

    int warp = (((int)blockIdx.x - fillBlocks) * 256 + (int)threadIdx.x) >> 5;
    int lane = threadIdx.x & 31;
    if (warp >= n) return;

    float xv = (lane < NF) ? x[warp * NF + lane] : 0.f;
    float a = sbe1[lane], b = sbe1[lane + 32];
#pragma unroll
    for (int k = 0; k < NF; k++) {
        float xk = __shfl_sync(0xffffffffu, xv, k);
        a = fmaf(xk, sWe1[k * H1 + lane], a);
        b = fmaf(xk, sWe1[k * H1 + lane + 32], b);
    }
    a = tanhf(a);
    b = tanhf(b);

    float acc = sbe2[lane];
#pragma unroll
    for (int j = 0; j < 32; j++) {
        float ha = __shfl_sync(0xffffffffu, a, j);
        float hb = __shfl_sync(0xffffffffu, b, j);
        acc = fmaf(ha, sWe2[j * D + lane], acc);
        acc = fmaf(hb, sWe2[(j + 32) * D + lane], acc);
    }
    float h = tanhf(acc);

    float hw = 0.f;
#pragma unroll
    for (int k = 0; k < 32; k++)
        hw = fmaf(__shfl_sync(0xffffffffu, h, k), sWg1[k * D + lane], hw);

    g_g1h[warp * D + lane] = __float2half(hw * g_dinv[warp]);
}

// ---------------- gather conv1 + relu + conv2 linear -------------------------
__global__ void __launch_bounds__(256) k_gather1(
    const float* __restrict__ Wg2, const float* __restrict__ bg1, int n)
{
    __shared__ float sW[D * D], sb[D];
    for (int i = threadIdx.x; i < D * D; i += 256) sW[i] = Wg2[i];
    for (int i = threadIdx.x; i < D;     i += 256) sb[i] = bg1[i];
    __syncthreads();

    int warp = (blockIdx.x * 256 + threadIdx.x) >> 5;
    int lane = threadIdx.x & 31;
    if (warp >= n) return;

    int beg = g_rowptr[warp], end = g_rowptr[warp + 1];
    float a0 = __half2float(g_g1h[warp * D + lane]);  // self loop
    float a1 = 0.f, a2 = 0.f, a3 = 0.f;
    int e = beg;
    for (; e + 4 <= end; e += 4) {
        int s0 = g_csc[e], s1 = g_csc[e + 1], s2 = g_csc[e + 2], s3 = g_csc[e + 3];
        a0 += __half2float(g_g1h[s0 * D + lane]);
        a1 += __half2float(g_g1h[s1 * D + lane]);
        a2 += __half2float(g_g1h[s2 * D + lane]);
        a3 += __half2float(g_g1h[s3 * D + lane]);
    }
    for (; e < end; e++) a0 += __half2float(g_g1h[g_csc[e] * D + lane]);
    float acc = (a0 + a1) + (a2 + a3);

    float di = g_dinv[warp];
    float h = fmaxf(fmaf(acc, di, sb[lane]), 0.f);

    float hw = 0.f;
#pragma unroll
    for (int k = 0; k < 32; k++)
        hw = fmaf(__shfl_sync(0xffffffffu, h, k), sW[k * D + lane], hw);

    g_g2h[warp * D + lane] = __float2half(hw * di);
}

// ---------------- gather conv2 + relu + output MLP ---------------------------
__global__ void __launch_bounds__(256) k_post(
    const float* __restrict__ bg2,
    const float* __restrict__ Wp1, const float* __restrict__ bp1,
    const float* __restrict__ Wp2, const float* __restrict__ bp2,
    float* __restrict__ out, int n)
{
    __shared__ float sW[D * D], sbg[D], sb1[D], sW2[D];
    __shared__ float sb2;
    for (int i = threadIdx.x; i < D * D; i += 256) sW[i] = Wp1[i];
    for (int i = threadIdx.x; i < D;     i += 256) { sbg[i] = bg2[i]; sb1[i] = bp1[i]; sW2[i] = Wp2[i]; }
    if (threadIdx.x == 0) sb2 = bp2[0];
    __syncthreads();

    int warp = (blockIdx.x * 256 + threadIdx.x) >> 5;
    int lane = threadIdx.x & 31;
    if (warp >= n) return;

    int beg = g_rowptr[warp], end = g_rowptr[warp + 1];
    float a0 = __half2float(g_g2h[warp * D + lane]);
    float a1 = 0.f, a2 = 0.f, a3 = 0.f;
    int e = beg;
    for (; e + 4 <= end; e += 4) {
        int s0 = g_csc[e], s1 = g_csc[e + 1], s2 = g_csc[e + 2], s3 = g_csc[e + 3];
        a0 += __half2float(g_g2h[s0 * D + lane]);
        a1 += __half2float(g_g2h[s1 * D + lane]);
        a2 += __half2float(g_g2h[s2 * D + lane]);
        a3 += __half2float(g_g2h[s3 * D + lane]);
    }
    for (; e < end; e++) a0 += __half2float(g_g2h[g_csc[e] * D + lane]);
    float acc = (a0 + a1) + (a2 + a3);

    float di = g_dinv[warp];
    float h = fmaxf(fmaf(acc, di, sbg[lane]), 0.f);

    float t = sb1[lane];
#pragma unroll
    for (int k = 0; k < 32; k++)
        t = fmaf(__shfl_sync(0xffffffffu, h, k), sW[k * D + lane], t);

    float u = tanhf(t) * sW2[lane];
#pragma unroll
    for (int off = 16; off; off >>= 1)
        u += __shfl_xor_sync(0xffffffffu, u, off);

    if (lane == 0) out[warp] = tanhf(u + sb2);
}

// ---------------- launch ------------------------------------------------------
extern "C" void kernel_launch(void* const* d_in, const int* in_sizes, int n_in,
                              void* d_out, int out_size)
{
    const float* x   = (const float*)d_in[0];
    const void*  ei  = d_in[1];
    const float* We1 = (const float*)d_in[2];
    const float* be1 = (const float*)d_in[3];
    const float* We2 = (const float*)d_in[4];
    const float* be2 = (const float*)d_in[5];
    const float* Wg1 = (const float*)d_in[6];
    const float* bg1 = (const float*)d_in[7];
    const float* Wg2 = (const float*)d_in[8];
    const float* bg2 = (const float*)d_in[9];
    const float* Wp1 = (const float*)d_in[10];
    const float* bp1 = (const float*)d_in[11];
    const float* Wp2 = (const float*)d_in[12];
    const float* bp2 = (const float*)d_in[13];

    int N = in_sizes[0] / NF;
    int E = in_sizes[1] / 2;
    if (N > MAXN) N = MAXN;
    if (E > MAXE) E = MAXE;

    k_init<<<(N + 255) / 256, 256>>>((const int*)ei, N);
    k_hist<<<(E + 255) / 256, 256>>>(ei, E);
    int nblk = (N + 1023) / 1024;
    k_scanA<<<nblk, 1024>>>(N);
    k_scanB<<<1, 128>>>(nblk);
    k_scanC<<<(N + 255) / 256, 256>>>(N, E);

    int fillBlocks = (E + 255) / 256;
    int nodeBlocks = (N * 32 + 255) / 256;
    k_fill_embed<<<fillBlocks + nodeBlocks, 256>>>(ei, E, fillBlocks,
                                                   x, We1, be1, We2, be2, Wg1, N);
    k_gather1<<<nodeBlocks, 256>>>(Wg2, bg1, N);
    k_post<<<nodeBlocks, 256>>>(bg2, Wp1, bp1, Wp2, bp2, (float*)d_out, N);
}